// round 15
// baseline (speedup 1.0000x reference)
#include <cuda_runtime.h>
#include <cstdint>

// PosRegressor_43482248904949 — batched bilinear shift with mirror boundary.
// images: (256,512,512,1) fp32, dxdy: (256,2) fp32 -> out: (256,512,512) fp32.
//
// R12: R11 body, 32-row blocks, FOUR 4-row tiles per warp off ONE prefix.
//  - per-warp setup (dependent dxdy load + floor/mirror ALU) amortized over
//    16 rows (was 8).
//  - 3 of 4 tile seams reload their shared input row from L1 (was 1 of 2).
//  - tiles statically unrolled off scalar state; v[] dead between tiles =>
//    peak regs == R8/R11 (64), no spills (R10's failure mode avoided).
//  - launch-per-tile grid (4096 blocks, ~7 waves) — persistence rejected.

#define H 512
#define W 512
#define NTHREADS 256

__device__ __forceinline__ int mirror_idx(int idx, int n) {
    const int p = 2 * (n - 1);
    int i = idx < 0 ? -idx : idx;
    i %= p;
    return (i >= n) ? (p - i) : i;
}

template <int M>
__device__ __forceinline__ void run_tile(
    const float* __restrict__ imb,
    float* __restrict__ outp,
    const int* __restrict__ roff,    // 5 mirrored input row offsets (elems)
    int a0,                          // 4-aligned input start column
    float fx, float fy)
{
    // ---- Load phase: 10 independent LDG.128 front-batched (deep MLP).
    float v[5][8];
    const bool interior = (a0 >= 0) & (a0 + 7 < W);
    if (interior) {
        #pragma unroll
        for (int r = 0; r < 5; ++r) {
            const float4 A = *reinterpret_cast<const float4*>(imb + roff[r] + a0);
            const float4 B = *reinterpret_cast<const float4*>(imb + roff[r] + a0 + 4);
            v[r][0]=A.x; v[r][1]=A.y; v[r][2]=A.z; v[r][3]=A.w;
            v[r][4]=B.x; v[r][5]=B.y; v[r][6]=B.z; v[r][7]=B.w;
        }
    } else {
        #pragma unroll
        for (int r = 0; r < 5; ++r)
            #pragma unroll
            for (int e = 0; e < 8; ++e)
                v[r][e] = imb[roff[r] + mirror_idx(a0 + e, W)];
    }

    // ---- Horizontal lerp (constant fx), window at uniform offset M.
    float h[5][4];
    #pragma unroll
    for (int r = 0; r < 5; ++r)
        #pragma unroll
        for (int j = 0; j < 4; ++j)
            h[r][j] = fmaf(fx, v[r][M + j + 1] - v[r][M + j], v[r][M + j]);

    // ---- Vertical lerp + streaming STG.128.
    #pragma unroll
    for (int r = 0; r < 4; ++r) {
        float4 o;
        o.x = fmaf(fy, h[r + 1][0] - h[r][0], h[r][0]);
        o.y = fmaf(fy, h[r + 1][1] - h[r][1], h[r][1]);
        o.z = fmaf(fy, h[r + 1][2] - h[r][2], h[r][2]);
        o.w = fmaf(fy, h[r + 1][3] - h[r][3], h[r][3]);
        __stcs(reinterpret_cast<float4*>(outp), o);
        outp += W;
    }
}

template <int M>
__device__ __forceinline__ void run_quad(
    const float* __restrict__ imb,
    float* __restrict__ outp,
    int ybase,                       // input row base for tile 0
    int a0, float fx, float fy)
{
    #pragma unroll
    for (int tq = 0; tq < 4; ++tq) {
        int roff[5];
        #pragma unroll
        for (int r = 0; r < 5; ++r)
            roff[r] = mirror_idx(ybase + 4 * tq + r, H) * W;  // seam rows: L1 hits
        run_tile<M>(imb, outp + 4 * tq * W, roff, a0, fx, fy);
    }
}

__global__ void __launch_bounds__(NTHREADS, 4)
shift_bilinear_kernel(const float* __restrict__ img,
                      const float* __restrict__ dxdy,
                      float* __restrict__ out) {
    const int b    = blockIdx.y;
    const int yb   = blockIdx.x * 32;       // 32 output rows per block
    const int tid  = threadIdx.x;
    const int wid  = tid >> 5;
    const int lane = tid & 31;

    const int cw = (wid & 3) * 128;         // warp column tile
    const int h0 = (wid >> 2) * 16;         // warp row range: [h0, h0+16)
    const int cq = cw + 4 * lane;           // this thread's output quad column

    const float2 d2 = *reinterpret_cast<const float2*>(dxdy + 2 * b);
    const float ndx = -d2.y, ndy = -d2.x;   // dy = d2.x, dx = d2.y
    const float kxf = floorf(ndx); const int kx = (int)kxf; const float fx = ndx - kxf;
    const float kyf = floorf(ndy); const int ky = (int)kyf; const float fy = ndy - kyf;

    const int m  = kx & 3;                  // uniform across all threads
    const int a0 = cq + kx - m;             // 4-aligned input start

    const size_t base = (size_t)b * (H * W);
    const float* __restrict__ imb = img + base;
    float* __restrict__ outp = out + base + (size_t)(yb + h0) * W + cq;

    const int ybase = yb + ky + h0;

    switch (m) {
        case 0: run_quad<0>(imb, outp, ybase, a0, fx, fy); break;
        case 1: run_quad<1>(imb, outp, ybase, a0, fx, fy); break;
        case 2: run_quad<2>(imb, outp, ybase, a0, fx, fy); break;
        default: run_quad<3>(imb, outp, ybase, a0, fx, fy); break;
    }
}

extern "C" void kernel_launch(void* const* d_in, const int* in_sizes, int n_in,
                              void* d_out, int out_size) {
    const float* images = (const float*)d_in[0];  // (256,512,512,1)
    const float* dxdy   = (const float*)d_in[1];  // (256,2)
    float* out = (float*)d_out;                   // (256,512,512)

    const int B = in_sizes[1] / 2;                // 256
    dim3 grid(H / 32, B);
    shift_bilinear_kernel<<<grid, NTHREADS>>>(images, dxdy, out);
}

// round 16
// speedup vs baseline: 1.0419x; 1.0419x over previous
#include <cuda_runtime.h>
#include <cstdint>

// PosRegressor_43482248904949 — batched bilinear shift with mirror boundary.
// images: (256,512,512,1) fp32, dxdy: (256,2) fp32 -> out: (256,512,512) fp32.
//
// R13 == R11 (best measured: 84.0us bench / 79.0us ncu, DRAM 77%).
// R12 (4-tile amortization) was neutral-regressed -> reverted per kill-criterion.
//
// Structure: dx,dy per-image scalars => integer shift (kx,ky) + constant
// weights (fx,fy); misalignment m = kx&3 is uniform => static register-window
// select. 16-row blocks, each warp runs two 4-row tiles off ONE prefix:
//  - 10 front-batched LDG.128 per tile (deep MLP)
//  - seam row between halves reloads from L1
//  - streaming STG.128 (__stcs): output never re-read, preserve L2 for input
//  - regs 64 (launch_bounds 256,4), no spills, no smem, no syncs.

#define H 512
#define W 512
#define NTHREADS 256

__device__ __forceinline__ int mirror_idx(int idx, int n) {
    const int p = 2 * (n - 1);
    int i = idx < 0 ? -idx : idx;
    i %= p;
    return (i >= n) ? (p - i) : i;
}

template <int M>
__device__ __forceinline__ void run_tile(
    const float* __restrict__ imb,
    float* __restrict__ outp,
    const int* __restrict__ roff,    // 5 mirrored input row offsets (elems)
    int a0,                          // 4-aligned input start column
    float fx, float fy)
{
    // ---- Load phase: 10 independent LDG.128 front-batched (deep MLP).
    float v[5][8];
    const bool interior = (a0 >= 0) & (a0 + 7 < W);
    if (interior) {
        #pragma unroll
        for (int r = 0; r < 5; ++r) {
            const float4 A = *reinterpret_cast<const float4*>(imb + roff[r] + a0);
            const float4 B = *reinterpret_cast<const float4*>(imb + roff[r] + a0 + 4);
            v[r][0]=A.x; v[r][1]=A.y; v[r][2]=A.z; v[r][3]=A.w;
            v[r][4]=B.x; v[r][5]=B.y; v[r][6]=B.z; v[r][7]=B.w;
        }
    } else {
        #pragma unroll
        for (int r = 0; r < 5; ++r)
            #pragma unroll
            for (int e = 0; e < 8; ++e)
                v[r][e] = imb[roff[r] + mirror_idx(a0 + e, W)];
    }

    // ---- Horizontal lerp (constant fx), window at uniform offset M.
    float h[5][4];
    #pragma unroll
    for (int r = 0; r < 5; ++r)
        #pragma unroll
        for (int j = 0; j < 4; ++j)
            h[r][j] = fmaf(fx, v[r][M + j + 1] - v[r][M + j], v[r][M + j]);

    // ---- Vertical lerp + streaming STG.128.
    #pragma unroll
    for (int r = 0; r < 4; ++r) {
        float4 o;
        o.x = fmaf(fy, h[r + 1][0] - h[r][0], h[r][0]);
        o.y = fmaf(fy, h[r + 1][1] - h[r][1], h[r][1]);
        o.z = fmaf(fy, h[r + 1][2] - h[r][2], h[r][2]);
        o.w = fmaf(fy, h[r + 1][3] - h[r][3], h[r][3]);
        __stcs(reinterpret_cast<float4*>(outp), o);
        outp += W;
    }
}

template <int M>
__device__ __forceinline__ void run_pair(
    const float* __restrict__ imb,
    float* __restrict__ outp,
    int ybase,                       // input row base for half 1
    int a0, float fx, float fy)
{
    int roff[5];
    #pragma unroll
    for (int r = 0; r < 5; ++r)
        roff[r] = mirror_idx(ybase + r, H) * W;
    run_tile<M>(imb, outp, roff, a0, fx, fy);

    #pragma unroll
    for (int r = 0; r < 5; ++r)
        roff[r] = mirror_idx(ybase + 4 + r, H) * W;   // row 4 reloads from L1
    run_tile<M>(imb, outp + 4 * W, roff, a0, fx, fy);
}

__global__ void __launch_bounds__(NTHREADS, 4)
shift_bilinear_kernel(const float* __restrict__ img,
                      const float* __restrict__ dxdy,
                      float* __restrict__ out) {
    const int b    = blockIdx.y;
    const int yb   = blockIdx.x * 16;       // 16 output rows per block
    const int tid  = threadIdx.x;
    const int wid  = tid >> 5;
    const int lane = tid & 31;

    const int cw = (wid & 3) * 128;         // warp column tile
    const int h0 = (wid >> 2) * 8;          // warp row range: [h0, h0+8)
    const int cq = cw + 4 * lane;           // this thread's output quad column

    const float2 d2 = *reinterpret_cast<const float2*>(dxdy + 2 * b);
    const float ndx = -d2.y, ndy = -d2.x;   // dy = d2.x, dx = d2.y
    const float kxf = floorf(ndx); const int kx = (int)kxf; const float fx = ndx - kxf;
    const float kyf = floorf(ndy); const int ky = (int)kyf; const float fy = ndy - kyf;

    const int m  = kx & 3;                  // uniform across all threads
    const int a0 = cq + kx - m;             // 4-aligned input start

    const size_t base = (size_t)b * (H * W);
    const float* __restrict__ imb = img + base;
    float* __restrict__ outp = out + base + (size_t)(yb + h0) * W + cq;

    const int ybase = yb + ky + h0;

    switch (m) {
        case 0: run_pair<0>(imb, outp, ybase, a0, fx, fy); break;
        case 1: run_pair<1>(imb, outp, ybase, a0, fx, fy); break;
        case 2: run_pair<2>(imb, outp, ybase, a0, fx, fy); break;
        default: run_pair<3>(imb, outp, ybase, a0, fx, fy); break;
    }
}

extern "C" void kernel_launch(void* const* d_in, const int* in_sizes, int n_in,
                              void* d_out, int out_size) {
    const float* images = (const float*)d_in[0];  // (256,512,512,1)
    const float* dxdy   = (const float*)d_in[1];  // (256,2)
    float* out = (float*)d_out;                   // (256,512,512)

    const int B = in_sizes[1] / 2;                // 256
    dim3 grid(H / 16, B);
    shift_bilinear_kernel<<<grid, NTHREADS>>>(images, dxdy, out);
}